// round 17
// baseline (speedup 1.0000x reference)
#include <cuda_runtime.h>
#include <cuda_bf16.h>
#include <cstdint>

// Problem constants
#define BATCH 32
#define SEQ   1024
#define HID   1024
#define WIN   128
#define KSUB  6
#define NHEAD 16
#define HD    64
#define NWIN  (BATCH * WIN)        // 4096
#define NROWS (NWIN * KSUB)        // 24576

// GEMM tiling: 96 compacted rows x 1 head (N=128), 256 threads, 3 CTAs/SM
#define MT 96
#define NT 128
#define KC 64                      // k per stage (128 B rows)
#define STAGES 2
#define NKITER (HID / KC)          // 16
#define MAXTILES 264

#define ASTR 72                    // bf16 elems per A row in smem (64 + 8 pad)
#define BSTR 72
#define A_ELEMS (MT * ASTR)        // 6912
#define B_ELEMS (NT * BSTR)        // 9216
#define STAGE_ELEMS (A_ELEMS + B_ELEMS)       // 16128
#define STAGE_BYTES (STAGE_ELEMS * 2)         // 32256
#define SMEM_BYTES  (STAGE_BYTES * STAGES)    // 64512

#define SQH 136                    // bf16 stride (128 + 8 pad)

__device__ __nv_bfloat16 g_Xc[(size_t)MAXTILES * 96 * HID];  // compacted rows, bf16
__device__ __nv_bfloat16 g_Wb[(size_t)2048 * HID];           // [head][q64|k64][1024]
__device__ float g_contribH[(size_t)NHEAD * NROWS];          // only j<len written; rest stay 0
__device__ int g_rowStart[NWIN];
__device__ int g_winList[NWIN];
__device__ int g_tileOff[6];
__device__ int g_winOff[6];
__device__ int g_nTiles;

__device__ __forceinline__ void cp16(uint32_t dst, const void* src) {
    asm volatile("cp.async.cg.shared.global [%0], [%1], 16;\n" :: "r"(dst), "l"(src));
}
__device__ __forceinline__ void cp_commit() {
    asm volatile("cp.async.commit_group;\n" ::: "memory");
}
__device__ __forceinline__ void ldsm_x4(uint32_t r[4], uint32_t addr) {
    asm volatile("ldmatrix.sync.aligned.m8n8.x4.shared.b16 {%0,%1,%2,%3}, [%4];"
                 : "=r"(r[0]), "=r"(r[1]), "=r"(r[2]), "=r"(r[3]) : "r"(addr));
}
__device__ __forceinline__ void mma_bf16(float c[4], uint32_t a0, uint32_t a1,
                                         uint32_t a2, uint32_t a3,
                                         uint32_t b0, uint32_t b1) {
    asm volatile(
        "mma.sync.aligned.m16n8k16.row.col.f32.bf16.bf16.f32 "
        "{%0,%1,%2,%3}, {%4,%5,%6,%7}, {%8,%9}, {%0,%1,%2,%3};\n"
        : "+f"(c[0]), "+f"(c[1]), "+f"(c[2]), "+f"(c[3])
        : "r"(a0), "r"(a1), "r"(a2), "r"(a3), "r"(b0), "r"(b1));
}

// ---------------------------------------------------------------------------
// Prepass: window lengths -> length buckets -> tile schedule + row placement.
// ---------------------------------------------------------------------------
__global__ void __launch_bounds__(256)
prepass_kernel(const int* __restrict__ idx) {
    __shared__ int cnt[5], base[5], toff[5], off[5];
    int tid = threadIdx.x;
    if (tid < 5) cnt[tid] = 0;
    __syncthreads();
    int lens[16];
#pragma unroll
    for (int t = 0; t < 16; t++) {
        int bw = tid * 16 + t;
        int L = 0;
#pragma unroll
        for (int k = 0; k < KSUB; k++) {
            int id = idx[bw * KSUB + k];
            if (id != 0 || (((bw & (WIN - 1)) == 0) && k == 0)) L++;
        }
        L = max(2, min(6, L));
        lens[t] = L;
        atomicAdd(&cnt[L - 2], 1);
    }
    __syncthreads();
    if (tid == 0) {
        int wacc = 0, tacc = 0;
        for (int b = 0; b < 5; b++) {
            int wpt = 96 / (b + 2);
            base[b] = wacc; toff[b] = tacc;
            g_winOff[b] = wacc; g_tileOff[b] = tacc;
            wacc += cnt[b];
            tacc += (cnt[b] + wpt - 1) / wpt;
            off[b] = base[b];
        }
        g_winOff[5] = wacc; g_tileOff[5] = tacc;
        g_nTiles = tacc;
    }
    __syncthreads();
#pragma unroll
    for (int t = 0; t < 16; t++) {
        int bw = tid * 16 + t;
        int L = lens[t];
        int b = L - 2;
        int wpt = 96 / L;
        int pos = atomicAdd(&off[b], 1);
        g_winList[pos] = bw;
        int p = pos - base[b];
        int tile = toff[b] + p / wpt;
        g_rowStart[bw] = tile * 96 + (p % wpt) * L;
    }
}

// ---------------------------------------------------------------------------
// Convert & permute W[:2048] -> g_Wb, row order [head][q(64)|k(64)].
// ---------------------------------------------------------------------------
__global__ void __launch_bounds__(256)
prep_w_kernel(const float* __restrict__ Wt) {
    int o = blockIdx.x;
    int t = threadIdx.x;
    int h = o >> 7;
    int r = o & 127;
    int src = ((r >= 64) ? HID : 0) + h * HD + (r & 63);
    float4 v = reinterpret_cast<const float4*>(Wt)[(size_t)src * 256 + t];
    __nv_bfloat162 lo = __floats2bfloat162_rn(v.x, v.y);
    __nv_bfloat162 hi = __floats2bfloat162_rn(v.z, v.w);
    uint2 pk;
    pk.x = *reinterpret_cast<uint32_t*>(&lo);
    pk.y = *reinterpret_cast<uint32_t*>(&hi);
    reinterpret_cast<uint2*>(g_Wb)[(size_t)o * 256 + t] = pk;
}

// ---------------------------------------------------------------------------
// Fused passthrough + gather (scatter covered rows into compacted g_Xc).
// ---------------------------------------------------------------------------
__global__ void __launch_bounds__(256)
fused_pass_kernel(const float* __restrict__ emb, const int* __restrict__ idx,
                  float* __restrict__ out) {
    int gid = blockIdx.x * 256 + threadIdx.x;   // float4 index
    int sg = gid >> 8;
    int s = sg & (SEQ - 1);
    int t = gid & 255;
    int k = s & 7;
    int bw = (sg >> 10) * WIN + (s >> 3);
    bool covered = false;
    if (k < KSUB) {
        int id = idx[bw * KSUB + k];
        covered = (id != 0) || (s == 0);
    }
    float4 v = reinterpret_cast<const float4*>(emb)[gid];
    float4 z = make_float4(0.f, 0.f, 0.f, 0.f);
    reinterpret_cast<float4*>(out)[gid] = covered ? z : v;
    if (covered) {
        int row = g_rowStart[bw] + k;
        __nv_bfloat162 lo = __floats2bfloat162_rn(v.x, v.y);
        __nv_bfloat162 hi = __floats2bfloat162_rn(v.z, v.w);
        uint2 pk;
        pk.x = *reinterpret_cast<uint32_t*>(&lo);
        pk.y = *reinterpret_cast<uint32_t*>(&hi);
        reinterpret_cast<uint2*>(g_Xc)[(size_t)row * 256 + t] = pk;
    }
}

// ---------------------------------------------------------------------------
// bf16 GEMM over compacted tiles (1 head) + fused scores/softmax/contrib.
// grid = (264, 16), 256 threads, 3 CTAs/SM.
// ---------------------------------------------------------------------------
__global__ void __launch_bounds__(256, 3)
gemm_scores_kernel(const float* __restrict__ bias) {
    extern __shared__ char smem_raw[];
    __nv_bfloat16* sQKh = reinterpret_cast<__nv_bfloat16*>(smem_raw); // [96][SQH]
    float* sAT = reinterpret_cast<float*>(smem_raw + MT * SQH * 2);   // [96][6]
    float* sBK = sAT + MT * KSUB;                                     // [64] k-bias

    const int tile = blockIdx.x;
    if (tile >= g_nTiles) return;
    const int by = blockIdx.y;        // head
    const int tid = threadIdx.x;
    const int warp = tid >> 5;
    const int lane = tid & 31;
    const int g = lane >> 2;
    const int c = lane & 3;
    const int mw = warp >> 2;         // 0..1 (M half)
    const int nw = warp & 3;          // 0..3 (32-col slice)

    // tile schedule
    int b = 0;
#pragma unroll
    for (int i = 1; i < 5; i++) if (tile >= g_tileOff[i]) b = i;
    const int L = b + 2;
    const int wpt = 96 / L;
    const int lt = tile - g_tileOff[b];
    const int winBase = g_winOff[b] + lt * wpt;
    const int bcnt = g_winOff[b + 1] - g_winOff[b];
    const int nwin = min(wpt, bcnt - lt * wpt);
    const int rows = nwin * L;

    const size_t arow0 = (size_t)tile * 96;
    const int wrow0 = by * NT;
    const uint32_t smem_u32 = (uint32_t)__cvta_generic_to_shared(smem_raw);

    const int ar = mw * 48 + ((lane >> 3) & 1) * 8 + (lane & 7);
    const int ac = (lane >> 4) * 8;
    const uint32_t a_off = (uint32_t)(ar * ASTR + ac) * 2;
    const int br = nw * 32 + ((lane >> 4) & 1) * 8 + (lane & 7);
    const int bc = ((lane >> 3) & 1) * 8;
    const uint32_t b_off = (uint32_t)A_ELEMS * 2 + (uint32_t)(br * BSTR + bc) * 2;

    float acc[3][4][4];
#pragma unroll
    for (int m = 0; m < 3; m++)
#pragma unroll
        for (int n = 0; n < 4; n++)
#pragma unroll
            for (int e = 0; e < 4; e++) acc[m][n][e] = 0.f;

    // KC=64 stage: A = 96 rows x 128 B (768 chunks, 3/thread),
    //              B = 128 rows x 128 B (1024 chunks, 4/thread)
    auto issue = [&](int s, int kk) {
        uint32_t base = smem_u32 + (uint32_t)(s & 1) * STAGE_BYTES;
        const __nv_bfloat16* asrc = g_Xc + arow0 * HID + kk;
#pragma unroll
        for (int t = 0; t < 3; t++) {
            int i = tid + t * 256;
            int r = i >> 3, cc = i & 7;
            cp16(base + r * (ASTR * 2) + cc * 16, asrc + (size_t)r * HID + cc * 8);
        }
        const __nv_bfloat16* bsrc = g_Wb + (size_t)wrow0 * HID + kk;
        uint32_t bbase = base + A_ELEMS * 2;
#pragma unroll
        for (int t = 0; t < 4; t++) {
            int i = tid + t * 256;
            int r = i >> 3, cc = i & 7;
            cp16(bbase + r * (BSTR * 2) + cc * 16, bsrc + (size_t)r * HID + cc * 8);
        }
    };

    issue(0, 0); cp_commit();

    for (int it = 0; it < NKITER; ++it) {
        asm volatile("cp.async.wait_group 0;\n" ::: "memory");
        __syncthreads();
        if (it + 1 < NKITER) { issue(it + 1, (it + 1) * KC); cp_commit(); }

        uint32_t stage_base = smem_u32 + (uint32_t)(it & 1) * STAGE_BYTES;
#pragma unroll
        for (int ks = 0; ks < 4; ks++) {
            const int kb = ks * 16;
            uint32_t a[3][4];
#pragma unroll
            for (int m = 0; m < 3; m++)
                ldsm_x4(a[m], stage_base + a_off + (uint32_t)(m * 16 * ASTR + kb) * 2);
#pragma unroll
            for (int np = 0; np < 2; np++) {
                uint32_t bfr[4];
                ldsm_x4(bfr, stage_base + b_off + (uint32_t)(np * 16 * BSTR + kb) * 2);
#pragma unroll
                for (int m = 0; m < 3; m++) {
                    mma_bf16(acc[m][np * 2 + 0], a[m][0], a[m][1], a[m][2], a[m][3],
                             bfr[0], bfr[1]);
                    mma_bf16(acc[m][np * 2 + 1], a[m][0], a[m][1], a[m][2], a[m][3],
                             bfr[2], bfr[3]);
                }
            }
        }
    }
    __syncthreads();

    // ---- epilogue: write QK tile (bias add, bf16) + stage k-bias ----
#pragma unroll
    for (int m = 0; m < 3; m++)
#pragma unroll
        for (int n = 0; n < 4; n++) {
            int row = mw * 48 + m * 16 + g;
            int col = nw * 32 + n * 8 + c * 2;
            int bidx = (col < HD) ? (by * HD + col) : (HID + by * HD + (col - HD));
            float b0v = bias[bidx], b1v = bias[bidx + 1];
            *reinterpret_cast<__nv_bfloat162*>(sQKh + row * SQH + col) =
                __floats2bfloat162_rn(acc[m][n][0] + b0v, acc[m][n][1] + b1v);
            *reinterpret_cast<__nv_bfloat162*>(sQKh + (row + 8) * SQH + col) =
                __floats2bfloat162_rn(acc[m][n][2] + b0v, acc[m][n][3] + b1v);
        }
    if (tid < 64)
        sBK[tid] = bias[HID + by * HD + tid];
    __syncthreads();

    // ---- scores + softmax over all 6 columns (one head) ----
    // Invalid columns (j >= L) have k-row == bias_k exactly (zeroed input row),
    // pair mask 0: score = q_i . bias_k / 8. They enter ONLY the denominator.
    if (tid < rows) {
        int r = tid;
        int wloc = r / L, i = r - wloc * L;
        int rbase = wloc * L;
        const __nv_bfloat162* qrow = reinterpret_cast<const __nv_bfloat162*>(
            sQKh + (rbase + i) * SQH);
        float sc[KSUB];
        float dinv = 0.f;
#pragma unroll
        for (int x = 0; x < HD / 2; x++) {
            float2 qv = __bfloat1622float2(qrow[x]);
            dinv += qv.x * sBK[2 * x] + qv.y * sBK[2 * x + 1];
        }
        dinv *= 0.125f;
#pragma unroll
        for (int j = 0; j < KSUB; j++) {
            if (j < L) {
                const __nv_bfloat162* krow = reinterpret_cast<const __nv_bfloat162*>(
                    sQKh + (rbase + j) * SQH + HD);
                float d = 0.f;
#pragma unroll
                for (int x = 0; x < HD / 2; x++) {
                    float2 qv = __bfloat1622float2(qrow[x]);
                    float2 kv = __bfloat1622float2(krow[x]);
                    d += qv.x * kv.x + qv.y * kv.y;
                }
                sc[j] = d * 0.125f + 1.0f;   // pair mask = 1 among valid rows
            } else sc[j] = dinv;
        }
        float mx = dinv;
#pragma unroll
        for (int j = 0; j < KSUB; j++) mx = fmaxf(mx, sc[j]);
        float ssum = 0.f;
        float e[KSUB];
#pragma unroll
        for (int j = 0; j < KSUB; j++) {
            e[j] = expf(sc[j] - mx);
            ssum += e[j];
        }
        float inv = 1.f / ssum;
#pragma unroll
        for (int j = 0; j < KSUB; j++)
            if (j < L) sAT[r * KSUB + j] = e[j] * inv;
    }
    __syncthreads();

    // ---- contrib (this head), * 1/NHEAD ----
    if (tid < rows) {
        int wloc = tid / L, j = tid - wloc * L;
        int rbase = wloc * L;
        float cv = 0.f;
#pragma unroll
        for (int i2 = 0; i2 < KSUB; i2++)
            if (i2 < L) cv += sAT[(rbase + i2) * KSUB + j];
        int bw = g_winList[winBase + wloc];
        g_contribH[(size_t)by * NROWS + bw * KSUB + j] = cv * (1.0f / (float)NHEAD);
    }
}

// ---------------------------------------------------------------------------
// Finalize: sum contrib over heads (gated by validity), normalize,
// fp32 gather-weighted sum, scatter to out[b, w*8].
// ---------------------------------------------------------------------------
__global__ void __launch_bounds__(256)
finalize_kernel(const float* __restrict__ emb, const int* __restrict__ idx,
                float* __restrict__ out) {
    int bw = blockIdx.x;
    __shared__ float scon[KSUB];
    __shared__ int sid[KSUB];
    if (threadIdx.x < KSUB) {
        int base = bw * KSUB + threadIdx.x;
        int id = idx[base];
        bool vk = (id != 0) || (((bw & (WIN - 1)) == 0) && threadIdx.x == 0);
        float s = 0.f;
#pragma unroll
        for (int by = 0; by < NHEAD; by++) s += g_contribH[(size_t)by * NROWS + base];
        scon[threadIdx.x] = vk ? s : 0.f;
        sid[threadIdx.x] = vk ? id : 0;
    }
    __syncthreads();
    float sum = scon[0] + scon[1] + scon[2] + scon[3] + scon[4] + scon[5];
    float inv = 1.0f / (sum + 1e-8f);
    int t = threadIdx.x;
    int b = bw >> 7;
    float4 u = make_float4(0.f, 0.f, 0.f, 0.f);
#pragma unroll
    for (int k = 0; k < KSUB; k++) {
        float cw = scon[k] * inv;
        float4 v = reinterpret_cast<const float4*>(emb)[(size_t)(b * SEQ + sid[k]) * 256 + t];
        u.x += cw * v.x; u.y += cw * v.y; u.z += cw * v.z; u.w += cw * v.w;
    }
    int w = bw & (WIN - 1);
    reinterpret_cast<float4*>(out)[(size_t)(b * SEQ + w * 8) * 256 + t] = u;
}

// ---------------------------------------------------------------------------
extern "C" void kernel_launch(void* const* d_in, const int* in_sizes, int n_in,
                              void* d_out, int out_size) {
    const float* emb  = (const float*)d_in[0];
    const float* Wt   = (const float*)d_in[1];
    const float* bias = (const float*)d_in[2];
    const int* idx    = (const int*)d_in[3];
    float* out = (float*)d_out;
    (void)in_sizes; (void)n_in; (void)out_size;

    cudaFuncSetAttribute(gemm_scores_kernel,
                         cudaFuncAttributeMaxDynamicSharedMemorySize, SMEM_BYTES);

    prepass_kernel<<<1, 256>>>(idx);
    prep_w_kernel<<<2048, 256>>>(Wt);
    fused_pass_kernel<<<(BATCH * SEQ * HID / 4) / 256, 256>>>(emb, idx, out);
    gemm_scores_kernel<<<dim3(MAXTILES, NHEAD), 256, SMEM_BYTES>>>(bias);
    finalize_kernel<<<NWIN, 256>>>(emb, idx, out);
}